// round 14
// baseline (speedup 1.0000x reference)
#include <cuda_runtime.h>
#include <cuda_bf16.h>
#include <math.h>
#include <stdint.h>

#define S_LEN 2048
#define HID   4096
#define NH    32
#define HD    128

typedef __nv_bfloat16  bf16;
typedef __nv_bfloat162 bf162;

// ===================== scratch (device globals; no cudaMalloc) =====================
__device__ bf16 g_Xhi[(size_t)S_LEN * HID];
__device__ bf16 g_Xlo[(size_t)S_LEN * HID];
__device__ bf16 g_Whi[4][(size_t)HID * HID];
__device__ bf16 g_Wlo[4][(size_t)HID * HID];
__device__ bf16 g_Qhi[(size_t)NH * S_LEN * HD];
__device__ bf16 g_Qlo[(size_t)NH * S_LEN * HD];
__device__ bf16 g_Khi[(size_t)NH * S_LEN * HD];
__device__ bf16 g_Klo[(size_t)NH * S_LEN * HD];
__device__ bf16 g_Vthi[(size_t)NH * HD * S_LEN];   // [h][d][t]
__device__ bf16 g_Vtlo[(size_t)NH * HD * S_LEN];
__device__ float g_P  [(size_t)NH * S_LEN * S_LEN];
__device__ bf16 g_Phi [(size_t)NH * S_LEN * S_LEN];
__device__ bf16 g_Plo [(size_t)NH * S_LEN * S_LEN];
__device__ bf16 g_Chi [(size_t)S_LEN * HID];
__device__ bf16 g_Clo [(size_t)S_LEN * HID];

// ===================== helpers =====================
static __device__ __forceinline__ uint32_t smem_u32(const void* p) {
    uint32_t a;
    asm("{ .reg .u64 t; cvta.to.shared.u64 t, %1; cvt.u32.u64 %0, t; }" : "=r"(a) : "l"(p));
    return a;
}

static __device__ __forceinline__ void cp_async16(uint32_t dst, const void* src) {
    asm volatile("cp.async.cg.shared.global [%0], [%1], 16;" :: "r"(dst), "l"(src));
}
#define CP_COMMIT()  asm volatile("cp.async.commit_group;" ::: "memory")
#define CP_WAIT(n)   asm volatile("cp.async.wait_group %0;" :: "n"(n) : "memory")

static __device__ __forceinline__ void ldsm_x4(uint32_t addr, uint32_t& r0, uint32_t& r1,
                                               uint32_t& r2, uint32_t& r3) {
    asm volatile("ldmatrix.sync.aligned.m8n8.x4.shared.b16 {%0,%1,%2,%3}, [%4];"
                 : "=r"(r0), "=r"(r1), "=r"(r2), "=r"(r3) : "r"(addr));
}

static __device__ __forceinline__ void mma16816(float* c, const uint32_t* a, const uint32_t* b) {
    asm volatile(
        "mma.sync.aligned.m16n8k16.row.col.f32.bf16.bf16.f32 "
        "{%0,%1,%2,%3}, {%4,%5,%6,%7}, {%8,%9}, {%0,%1,%2,%3};"
        : "+f"(c[0]), "+f"(c[1]), "+f"(c[2]), "+f"(c[3])
        : "r"(a[0]), "r"(a[1]), "r"(a[2]), "r"(a[3]), "r"(b[0]), "r"(b[1]));
}

static __device__ __forceinline__ void store_split(bf16* hi, bf16* lo, size_t idx, float v) {
    bf16 h = __float2bfloat16(v);
    hi[idx] = h;
    lo[idx] = __float2bfloat16(v - __bfloat162float(h));
}

// smem tile geometry: 128 rows x 32 bf16, row pitch 40 bf16 (80 B = 5 x 16B, odd -> ldmatrix conflict-free)
#define PITCH    40
#define TILE_B   (128 * PITCH * 2)      // 10240 bytes
#define STAGE_B  (4 * TILE_B)           // Ahi, Alo, Bhi, Blo = 40960 bytes
#define SMEM_TOT (2 * STAGE_B)          // double buffered = 81920 bytes

// ===================== split-bf16 mma.sync GEMM-NT =====================
// D[m][n] = sum_k A[m][k] * B[n][k]   (A,B hi/lo bf16 pairs, K-major, ld = K)
// MODE 0: fp32 out [M,HID] + bias                 (O projection)
// MODE 1: +bias, RoPE, split-store [h][s][d]      (Q / K)
// MODE 2: +bias, split-store transposed [h][d][t] (V)
// MODE 3: *1/sqrt(128) + mask -> fp32 g_P         (scores)
// MODE 4: split-store ctx [s][HID]                (PV)
template<int MODE>
__global__ void __launch_bounds__(256, 1)
mma_gemm(const bf16* __restrict__ Ahi, const bf16* __restrict__ Alo,
         const bf16* __restrict__ Bhi, const bf16* __restrict__ Blo,
         int K, long long batchA, long long batchB,
         const float* __restrict__ bias, const float* __restrict__ mask,
         const int* __restrict__ tsl_ptr,
         float* __restrict__ outF, bf16* __restrict__ Ohi, bf16* __restrict__ Olo)
{
    extern __shared__ char smem[];
    const uint32_t sbase = smem_u32(smem);

    const int tid  = threadIdx.x;
    const int wid  = tid >> 5;
    const int lane = tid & 31;
    const int wm   = wid >> 2;          // 0..1  -> 64-row slab
    const int wn   = wid & 3;           // 0..3  -> 32-col slab
    const int hz   = blockIdx.z;
    const int m0   = blockIdx.y * 128;
    const int n0   = blockIdx.x * 128;

    const bf16* srcs[4] = {
        Ahi + (size_t)hz * batchA + (size_t)m0 * K,
        Alo + (size_t)hz * batchA + (size_t)m0 * K,
        Bhi + (size_t)hz * batchB + (size_t)n0 * K,
        Blo + (size_t)hz * batchB + (size_t)n0 * K
    };

    // per-thread load slots: idx 0..511 -> row idx>>2, 16B-chunk idx&3
    const int l_r0 = tid >> 2,       l_c = (tid & 3) * 8;     // bf16 col offset
    const int l_r1 = (tid + 256) >> 2;

    auto load_stage = [&](int kc, int b) {
        const uint32_t stage = sbase + b * STAGE_B;
        #pragma unroll
        for (int t = 0; t < 4; ++t) {
            const bf16* s = srcs[t] + (size_t)kc * 32;
            const uint32_t dtile = stage + t * TILE_B;
            cp_async16(dtile + (l_r0 * PITCH + l_c) * 2, s + (size_t)l_r0 * K + l_c);
            cp_async16(dtile + (l_r1 * PITCH + l_c) * 2, s + (size_t)l_r1 * K + l_c);
        }
    };

    float acc[4][4][4];
    #pragma unroll
    for (int i = 0; i < 4; ++i)
        #pragma unroll
        for (int j = 0; j < 4; ++j)
            #pragma unroll
            for (int r = 0; r < 4; ++r) acc[i][j][r] = 0.f;

    const int NC = K >> 5;
    load_stage(0, 0);
    CP_COMMIT();

    // ldmatrix per-lane address offsets
    const int a_row  = lane & 15;                    // + mt*16 + wm*64
    const int a_koff = (lane & 16) ? 8 : 0;
    const int b_row  = (lane & 7) + ((lane & 16) ? 8 : 0);   // + pair*16 + wn*32
    const int b_koff = (lane & 8) ? 8 : 0;

    for (int kc = 0; kc < NC; ++kc) {
        if (kc + 1 < NC) { load_stage(kc + 1, (kc + 1) & 1); CP_COMMIT(); CP_WAIT(1); }
        else             { CP_WAIT(0); }
        __syncthreads();

        const uint32_t stage = sbase + (kc & 1) * STAGE_B;
        const uint32_t sAh = stage;
        const uint32_t sAl = stage + TILE_B;
        const uint32_t sBh = stage + 2 * TILE_B;
        const uint32_t sBl = stage + 3 * TILE_B;

        #pragma unroll
        for (int ks = 0; ks < 32; ks += 16) {
            uint32_t a_hi[4][4], a_lo[4][4], b_hi[4][2], b_lo[4][2];
            #pragma unroll
            for (int mt = 0; mt < 4; ++mt) {
                const uint32_t off =
                    ((wm * 64 + mt * 16 + a_row) * PITCH + ks + a_koff) * 2;
                ldsm_x4(sAh + off, a_hi[mt][0], a_hi[mt][1], a_hi[mt][2], a_hi[mt][3]);
                ldsm_x4(sAl + off, a_lo[mt][0], a_lo[mt][1], a_lo[mt][2], a_lo[mt][3]);
            }
            #pragma unroll
            for (int pr = 0; pr < 2; ++pr) {
                const uint32_t off =
                    ((wn * 32 + pr * 16 + b_row) * PITCH + ks + b_koff) * 2;
                ldsm_x4(sBh + off, b_hi[2 * pr][0], b_hi[2 * pr][1],
                                   b_hi[2 * pr + 1][0], b_hi[2 * pr + 1][1]);
                ldsm_x4(sBl + off, b_lo[2 * pr][0], b_lo[2 * pr][1],
                                   b_lo[2 * pr + 1][0], b_lo[2 * pr + 1][1]);
            }
            #pragma unroll
            for (int mt = 0; mt < 4; ++mt)
                #pragma unroll
                for (int nt = 0; nt < 4; ++nt) {
                    mma16816(acc[mt][nt], a_hi[mt], b_hi[nt]);
                    mma16816(acc[mt][nt], a_hi[mt], b_lo[nt]);
                    mma16816(acc[mt][nt], a_lo[mt], b_hi[nt]);
                }
        }
        __syncthreads();
    }

    // ===================== epilogue (straight from registers) =====================
    const int qid = lane >> 2;       // row within 8
    const int rid = lane & 3;        // col-pair id

    if (MODE == 1) {
        const int tslv = *tsl_ptr;
        #pragma unroll
        for (int mt = 0; mt < 4; ++mt)
            #pragma unroll
            for (int nt = 0; nt < 4; ++nt)
                #pragma unroll
                for (int half = 0; half < 2; ++half) {
                    int row  = m0 + wm * 64 + mt * 16 + qid + half * 8;
                    int gcol = n0 + wn * 32 + nt * 8 + rid * 2;   // even
                    float x1 = acc[mt][nt][2 * half]     + bias[gcol];
                    float x2 = acc[mt][nt][2 * half + 1] + bias[gcol + 1];
                    int hh = gcol >> 7, dd = gcol & 127;
                    float inv = expf((float)dd * (-9.210340371976184f / 128.f));
                    float pos = (float)(tslv - S_LEN + row);
                    float sn, cs;
                    sincosf(pos * inv, &sn, &cs);
                    float y1 = x1 * cs - x2 * sn;
                    float y2 = x1 * sn + x2 * cs;
                    size_t dst = ((size_t)hh * S_LEN + row) * HD + dd;
                    bf16 h1 = __float2bfloat16(y1), h2 = __float2bfloat16(y2);
                    *reinterpret_cast<bf162*>(Ohi + dst) = __halves2bfloat162(h1, h2);
                    bf16 l1 = __float2bfloat16(y1 - __bfloat162float(h1));
                    bf16 l2 = __float2bfloat16(y2 - __bfloat162float(h2));
                    *reinterpret_cast<bf162*>(Olo + dst) = __halves2bfloat162(l1, l2);
                }
    } else if (MODE == 2) {
        #pragma unroll
        for (int mt = 0; mt < 4; ++mt)
            #pragma unroll
            for (int nt = 0; nt < 4; ++nt)
                #pragma unroll
                for (int r = 0; r < 4; ++r) {
                    int row  = m0 + wm * 64 + mt * 16 + qid + (r >> 1) * 8;
                    int gcol = n0 + wn * 32 + nt * 8 + rid * 2 + (r & 1);
                    int hh = gcol >> 7, dd = gcol & 127;
                    float v = acc[mt][nt][r] + bias[gcol];
                    store_split(Ohi, Olo, ((size_t)hh * HD + dd) * S_LEN + row, v);
                }
    } else if (MODE == 3) {
        const float sc = 0.08838834764831845f;
        #pragma unroll
        for (int mt = 0; mt < 4; ++mt)
            #pragma unroll
            for (int nt = 0; nt < 4; ++nt)
                #pragma unroll
                for (int r = 0; r < 4; ++r) {
                    int row  = m0 + wm * 64 + mt * 16 + qid + (r >> 1) * 8;
                    int gcol = n0 + wn * 32 + nt * 8 + rid * 2 + (r & 1);
                    outF[((size_t)hz * S_LEN + row) * S_LEN + gcol] =
                        acc[mt][nt][r] * sc + mask[(size_t)row * S_LEN + gcol];
                }
    } else if (MODE == 4) {
        #pragma unroll
        for (int mt = 0; mt < 4; ++mt)
            #pragma unroll
            for (int nt = 0; nt < 4; ++nt)
                #pragma unroll
                for (int r = 0; r < 4; ++r) {
                    int row  = m0 + wm * 64 + mt * 16 + qid + (r >> 1) * 8;
                    int col  = n0 + wn * 32 + nt * 8 + rid * 2 + (r & 1);
                    store_split(Ohi, Olo,
                                (size_t)row * HID + (size_t)hz * HD + col,
                                acc[mt][nt][r]);
                }
    } else { // MODE 0
        #pragma unroll
        for (int mt = 0; mt < 4; ++mt)
            #pragma unroll
            for (int nt = 0; nt < 4; ++nt)
                #pragma unroll
                for (int r = 0; r < 4; ++r) {
                    int row  = m0 + wm * 64 + mt * 16 + qid + (r >> 1) * 8;
                    int gcol = n0 + wn * 32 + nt * 8 + rid * 2 + (r & 1);
                    outF[(size_t)row * HID + gcol] = acc[mt][nt][r] + bias[gcol];
                }
    }
}

// ===================== fp32 -> bf16 hi/lo split =====================
__global__ void split4_kernel(const float4* __restrict__ src, bf162* __restrict__ hi,
                              bf162* __restrict__ lo, size_t n4)
{
    for (size_t i = blockIdx.x * (size_t)blockDim.x + threadIdx.x; i < n4;
         i += (size_t)gridDim.x * blockDim.x) {
        float4 v = src[i];
        bf16 hx = __float2bfloat16(v.x), hy = __float2bfloat16(v.y);
        bf16 hz2 = __float2bfloat16(v.z), hw = __float2bfloat16(v.w);
        hi[2 * i]     = __halves2bfloat162(hx, hy);
        hi[2 * i + 1] = __halves2bfloat162(hz2, hw);
        lo[2 * i]     = __halves2bfloat162(__float2bfloat16(v.x - __bfloat162float(hx)),
                                           __float2bfloat16(v.y - __bfloat162float(hy)));
        lo[2 * i + 1] = __halves2bfloat162(__float2bfloat16(v.z - __bfloat162float(hz2)),
                                           __float2bfloat16(v.w - __bfloat162float(hw)));
    }
}

// ===================== softmax (rows of g_P) -> split bf16 P =====================
__global__ void __launch_bounds__(256)
softmax_kernel()
{
    const size_t row = blockIdx.x;
    const float* p = g_P + row * S_LEN;
    const int tid = threadIdx.x;

    float v[8];
    float mx = -3.4e38f;
    #pragma unroll
    for (int t = 0; t < 8; ++t) {
        v[t] = p[tid + t * 256];
        mx = fmaxf(mx, v[t]);
    }

    __shared__ float red[8];
    #pragma unroll
    for (int o = 16; o > 0; o >>= 1)
        mx = fmaxf(mx, __shfl_xor_sync(0xffffffffu, mx, o));
    if ((tid & 31) == 0) red[tid >> 5] = mx;
    __syncthreads();
    if (tid == 0) {
        float m = red[0];
        #pragma unroll
        for (int w = 1; w < 8; ++w) m = fmaxf(m, red[w]);
        red[0] = m;
    }
    __syncthreads();
    const float bmax = red[0];
    __syncthreads();

    float sum = 0.f;
    #pragma unroll
    for (int t = 0; t < 8; ++t) { v[t] = expf(v[t] - bmax); sum += v[t]; }
    #pragma unroll
    for (int o = 16; o > 0; o >>= 1)
        sum += __shfl_xor_sync(0xffffffffu, sum, o);
    if ((tid & 31) == 0) red[tid >> 5] = sum;
    __syncthreads();
    if (tid == 0) {
        float s = 0.f;
        #pragma unroll
        for (int w = 0; w < 8; ++w) s += red[w];
        red[0] = 1.f / s;
    }
    __syncthreads();
    const float inv = red[0];
    const size_t base = row * (size_t)S_LEN;
    #pragma unroll
    for (int t = 0; t < 8; ++t)
        store_split(g_Phi, g_Plo, base + tid + t * 256, v[t] * inv);
}

// ===================== launcher =====================
extern "C" void kernel_launch(void* const* d_in, const int* in_sizes, int n_in,
                              void* d_out, int out_size)
{
    const float* X    = (const float*)d_in[0];
    const float* mask = (const float*)d_in[1];
    const float* Wq   = (const float*)d_in[2];
    const float* bq   = (const float*)d_in[3];
    const float* Wk   = (const float*)d_in[4];
    const float* bk   = (const float*)d_in[5];
    const float* Wv   = (const float*)d_in[6];
    const float* bv   = (const float*)d_in[7];
    const float* Wo   = (const float*)d_in[8];
    const float* bo   = (const float*)d_in[9];
    const int*   tsl  = (const int*)d_in[10];
    float* out = (float*)d_out;

    bf16 *pXhi, *pXlo, *pWhi, *pWlo, *pQhi, *pQlo, *pKhi, *pKlo;
    bf16 *pVthi, *pVtlo, *pPhi, *pPlo, *pChi, *pClo;
    float *pP;
    cudaGetSymbolAddress((void**)&pXhi,  g_Xhi);
    cudaGetSymbolAddress((void**)&pXlo,  g_Xlo);
    cudaGetSymbolAddress((void**)&pWhi,  g_Whi);
    cudaGetSymbolAddress((void**)&pWlo,  g_Wlo);
    cudaGetSymbolAddress((void**)&pQhi,  g_Qhi);
    cudaGetSymbolAddress((void**)&pQlo,  g_Qlo);
    cudaGetSymbolAddress((void**)&pKhi,  g_Khi);
    cudaGetSymbolAddress((void**)&pKlo,  g_Klo);
    cudaGetSymbolAddress((void**)&pVthi, g_Vthi);
    cudaGetSymbolAddress((void**)&pVtlo, g_Vtlo);
    cudaGetSymbolAddress((void**)&pP,    g_P);
    cudaGetSymbolAddress((void**)&pPhi,  g_Phi);
    cudaGetSymbolAddress((void**)&pPlo,  g_Plo);
    cudaGetSymbolAddress((void**)&pChi,  g_Chi);
    cudaGetSymbolAddress((void**)&pClo,  g_Clo);

    cudaFuncSetAttribute(mma_gemm<0>, cudaFuncAttributeMaxDynamicSharedMemorySize, SMEM_TOT);
    cudaFuncSetAttribute(mma_gemm<1>, cudaFuncAttributeMaxDynamicSharedMemorySize, SMEM_TOT);
    cudaFuncSetAttribute(mma_gemm<2>, cudaFuncAttributeMaxDynamicSharedMemorySize, SMEM_TOT);
    cudaFuncSetAttribute(mma_gemm<3>, cudaFuncAttributeMaxDynamicSharedMemorySize, SMEM_TOT);
    cudaFuncSetAttribute(mma_gemm<4>, cudaFuncAttributeMaxDynamicSharedMemorySize, SMEM_TOT);

    const size_t WELEM = (size_t)HID * HID;
    split4_kernel<<<2048, 256>>>((const float4*)X,  (bf162*)pXhi, (bf162*)pXlo,
                                 (size_t)S_LEN * HID / 4);
    split4_kernel<<<4096, 256>>>((const float4*)Wq, (bf162*)(pWhi + 0 * WELEM),
                                 (bf162*)(pWlo + 0 * WELEM), WELEM / 4);
    split4_kernel<<<4096, 256>>>((const float4*)Wk, (bf162*)(pWhi + 1 * WELEM),
                                 (bf162*)(pWlo + 1 * WELEM), WELEM / 4);
    split4_kernel<<<4096, 256>>>((const float4*)Wv, (bf162*)(pWhi + 2 * WELEM),
                                 (bf162*)(pWlo + 2 * WELEM), WELEM / 4);
    split4_kernel<<<4096, 256>>>((const float4*)Wo, (bf162*)(pWhi + 3 * WELEM),
                                 (bf162*)(pWlo + 3 * WELEM), WELEM / 4);

    dim3 blk(256);
    dim3 gproj(HID / 128, S_LEN / 128, 1);            // 32 x 16
    mma_gemm<1><<<gproj, blk, SMEM_TOT>>>(pXhi, pXlo, pWhi + 0 * WELEM, pWlo + 0 * WELEM,
                                          HID, 0, 0, bq, nullptr, tsl, nullptr, pQhi, pQlo);
    mma_gemm<1><<<gproj, blk, SMEM_TOT>>>(pXhi, pXlo, pWhi + 1 * WELEM, pWlo + 1 * WELEM,
                                          HID, 0, 0, bk, nullptr, tsl, nullptr, pKhi, pKlo);
    mma_gemm<2><<<gproj, blk, SMEM_TOT>>>(pXhi, pXlo, pWhi + 2 * WELEM, pWlo + 2 * WELEM,
                                          HID, 0, 0, bv, nullptr, nullptr, nullptr, pVthi, pVtlo);

    dim3 gsc(S_LEN / 128, S_LEN / 128, NH);           // 16 x 16 x 32
    mma_gemm<3><<<gsc, blk, SMEM_TOT>>>(pQhi, pQlo, pKhi, pKlo,
                                        HD, (long long)S_LEN * HD, (long long)S_LEN * HD,
                                        nullptr, mask, nullptr, pP, nullptr, nullptr);

    softmax_kernel<<<NH * S_LEN, 256>>>();

    dim3 gpv(1, S_LEN / 128, NH);                     // 1 x 16 x 32
    mma_gemm<4><<<gpv, blk, SMEM_TOT>>>(pPhi, pPlo, pVthi, pVtlo,
                                        S_LEN, (long long)S_LEN * S_LEN, (long long)HD * S_LEN,
                                        nullptr, nullptr, nullptr, nullptr, pChi, pClo);

    mma_gemm<0><<<gproj, blk, SMEM_TOT>>>(pChi, pClo, pWhi + 3 * WELEM, pWlo + 3 * WELEM,
                                          HID, 0, 0, bo, nullptr, nullptr, out, nullptr, nullptr);
}

// round 15
// speedup vs baseline: 1.0004x; 1.0004x over previous
#include <cuda_runtime.h>
#include <cuda_bf16.h>
#include <math.h>
#include <stdint.h>

#define S_LEN 2048
#define HID   4096
#define NH    32
#define HD    128

typedef __nv_bfloat16  bf16;
typedef __nv_bfloat162 bf162;

// ===================== scratch (device globals; no cudaMalloc) =====================
__device__ bf16 g_Xhi[(size_t)S_LEN * HID];
__device__ bf16 g_Xlo[(size_t)S_LEN * HID];
__device__ bf16 g_Whi[4][(size_t)HID * HID];
__device__ bf16 g_Wlo[4][(size_t)HID * HID];
__device__ bf16 g_Qhi[(size_t)NH * S_LEN * HD];
__device__ bf16 g_Qlo[(size_t)NH * S_LEN * HD];
__device__ bf16 g_Khi[(size_t)NH * S_LEN * HD];
__device__ bf16 g_Klo[(size_t)NH * S_LEN * HD];
__device__ bf16 g_Vthi[(size_t)NH * HD * S_LEN];   // [h][d][t]
__device__ bf16 g_Vtlo[(size_t)NH * HD * S_LEN];
__device__ float g_P  [(size_t)NH * S_LEN * S_LEN];
__device__ bf16 g_Phi [(size_t)NH * S_LEN * S_LEN];
__device__ bf16 g_Plo [(size_t)NH * S_LEN * S_LEN];
__device__ bf16 g_Chi [(size_t)S_LEN * HID];
__device__ bf16 g_Clo [(size_t)S_LEN * HID];

// ===================== helpers =====================
static __device__ __forceinline__ uint32_t smem_u32(const void* p) {
    uint32_t a;
    asm("{ .reg .u64 t; cvta.to.shared.u64 t, %1; cvt.u32.u64 %0, t; }" : "=r"(a) : "l"(p));
    return a;
}

static __device__ __forceinline__ void cp_async16(uint32_t dst, const void* src) {
    asm volatile("cp.async.cg.shared.global [%0], [%1], 16;" :: "r"(dst), "l"(src));
}
#define CP_COMMIT()  asm volatile("cp.async.commit_group;" ::: "memory")
#define CP_WAIT(n)   asm volatile("cp.async.wait_group %0;" :: "n"(n) : "memory")

static __device__ __forceinline__ void ldsm_x4(uint32_t addr, uint32_t& r0, uint32_t& r1,
                                               uint32_t& r2, uint32_t& r3) {
    asm volatile("ldmatrix.sync.aligned.m8n8.x4.shared.b16 {%0,%1,%2,%3}, [%4];"
                 : "=r"(r0), "=r"(r1), "=r"(r2), "=r"(r3) : "r"(addr));
}

static __device__ __forceinline__ void mma16816(float* c, const uint32_t* a, const uint32_t* b) {
    asm volatile(
        "mma.sync.aligned.m16n8k16.row.col.f32.bf16.bf16.f32 "
        "{%0,%1,%2,%3}, {%4,%5,%6,%7}, {%8,%9}, {%0,%1,%2,%3};"
        : "+f"(c[0]), "+f"(c[1]), "+f"(c[2]), "+f"(c[3])
        : "r"(a[0]), "r"(a[1]), "r"(a[2]), "r"(a[3]), "r"(b[0]), "r"(b[1]));
}

static __device__ __forceinline__ void store_split(bf16* hi, bf16* lo, size_t idx, float v) {
    bf16 h = __float2bfloat16(v);
    hi[idx] = h;
    lo[idx] = __float2bfloat16(v - __bfloat162float(h));
}

// smem tile geometry: 128 rows x 32 bf16, row pitch 40 bf16 (80 B = 5 x 16B, odd -> ldmatrix conflict-free)
#define PITCH    40
#define TILE_B   (128 * PITCH * 2)      // 10240 bytes
#define STAGE_B  (4 * TILE_B)           // Ahi, Alo, Bhi, Blo = 40960 bytes
#define SMEM_TOT (2 * STAGE_B)          // double buffered = 81920 bytes

// ===================== split-bf16 mma.sync GEMM-NT =====================
// D[m][n] = sum_k A[m][k] * B[n][k]   (A,B hi/lo bf16 pairs, K-major, ld = K)
// MODE 0: fp32 out [M,HID] + bias                 (O projection)
// MODE 1: +bias, RoPE, split-store [h][s][d]      (Q / K)
// MODE 2: +bias, split-store transposed [h][d][t] (V)
// MODE 3: *1/sqrt(128) + mask -> fp32 g_P         (scores)
// MODE 4: split-store ctx [s][HID]                (PV)
template<int MODE>
__global__ void __launch_bounds__(256, 1)
mma_gemm(const bf16* __restrict__ Ahi, const bf16* __restrict__ Alo,
         const bf16* __restrict__ Bhi, const bf16* __restrict__ Blo,
         int K, long long batchA, long long batchB,
         const float* __restrict__ bias, const float* __restrict__ mask,
         const int* __restrict__ tsl_ptr,
         float* __restrict__ outF, bf16* __restrict__ Ohi, bf16* __restrict__ Olo)
{
    extern __shared__ char smem[];
    const uint32_t sbase = smem_u32(smem);

    const int tid  = threadIdx.x;
    const int wid  = tid >> 5;
    const int lane = tid & 31;
    const int wm   = wid >> 2;          // 0..1  -> 64-row slab
    const int wn   = wid & 3;           // 0..3  -> 32-col slab
    const int hz   = blockIdx.z;
    const int m0   = blockIdx.y * 128;
    const int n0   = blockIdx.x * 128;

    const bf16* srcs[4] = {
        Ahi + (size_t)hz * batchA + (size_t)m0 * K,
        Alo + (size_t)hz * batchA + (size_t)m0 * K,
        Bhi + (size_t)hz * batchB + (size_t)n0 * K,
        Blo + (size_t)hz * batchB + (size_t)n0 * K
    };

    // per-thread load slots: idx 0..511 -> row idx>>2, 16B-chunk idx&3
    const int l_r0 = tid >> 2,       l_c = (tid & 3) * 8;     // bf16 col offset
    const int l_r1 = (tid + 256) >> 2;

    auto load_stage = [&](int kc, int b) {
        const uint32_t stage = sbase + b * STAGE_B;
        #pragma unroll
        for (int t = 0; t < 4; ++t) {
            const bf16* s = srcs[t] + (size_t)kc * 32;
            const uint32_t dtile = stage + t * TILE_B;
            cp_async16(dtile + (l_r0 * PITCH + l_c) * 2, s + (size_t)l_r0 * K + l_c);
            cp_async16(dtile + (l_r1 * PITCH + l_c) * 2, s + (size_t)l_r1 * K + l_c);
        }
    };

    float acc[4][4][4];
    #pragma unroll
    for (int i = 0; i < 4; ++i)
        #pragma unroll
        for (int j = 0; j < 4; ++j)
            #pragma unroll
            for (int r = 0; r < 4; ++r) acc[i][j][r] = 0.f;

    const int NC = K >> 5;
    load_stage(0, 0);
    CP_COMMIT();

    // ldmatrix per-lane address offsets
    const int a_row  = lane & 15;                    // + mt*16 + wm*64
    const int a_koff = (lane & 16) ? 8 : 0;
    const int b_row  = (lane & 7) + ((lane & 16) ? 8 : 0);   // + pair*16 + wn*32
    const int b_koff = (lane & 8) ? 8 : 0;

    for (int kc = 0; kc < NC; ++kc) {
        if (kc + 1 < NC) { load_stage(kc + 1, (kc + 1) & 1); CP_COMMIT(); CP_WAIT(1); }
        else             { CP_WAIT(0); }
        __syncthreads();

        const uint32_t stage = sbase + (kc & 1) * STAGE_B;
        const uint32_t sAh = stage;
        const uint32_t sAl = stage + TILE_B;
        const uint32_t sBh = stage + 2 * TILE_B;
        const uint32_t sBl = stage + 3 * TILE_B;

        #pragma unroll
        for (int ks = 0; ks < 32; ks += 16) {
            uint32_t a_hi[4][4], a_lo[4][4], b_hi[4][2], b_lo[4][2];
            #pragma unroll
            for (int mt = 0; mt < 4; ++mt) {
                const uint32_t off =
                    ((wm * 64 + mt * 16 + a_row) * PITCH + ks + a_koff) * 2;
                ldsm_x4(sAh + off, a_hi[mt][0], a_hi[mt][1], a_hi[mt][2], a_hi[mt][3]);
                ldsm_x4(sAl + off, a_lo[mt][0], a_lo[mt][1], a_lo[mt][2], a_lo[mt][3]);
            }
            #pragma unroll
            for (int pr = 0; pr < 2; ++pr) {
                const uint32_t off =
                    ((wn * 32 + pr * 16 + b_row) * PITCH + ks + b_koff) * 2;
                ldsm_x4(sBh + off, b_hi[2 * pr][0], b_hi[2 * pr][1],
                                   b_hi[2 * pr + 1][0], b_hi[2 * pr + 1][1]);
                ldsm_x4(sBl + off, b_lo[2 * pr][0], b_lo[2 * pr][1],
                                   b_lo[2 * pr + 1][0], b_lo[2 * pr + 1][1]);
            }
            #pragma unroll
            for (int mt = 0; mt < 4; ++mt)
                #pragma unroll
                for (int nt = 0; nt < 4; ++nt) {
                    mma16816(acc[mt][nt], a_hi[mt], b_hi[nt]);
                    mma16816(acc[mt][nt], a_hi[mt], b_lo[nt]);
                    mma16816(acc[mt][nt], a_lo[mt], b_hi[nt]);
                }
        }
        __syncthreads();
    }

    // ===================== epilogue (straight from registers) =====================
    const int qid = lane >> 2;       // row within 8
    const int rid = lane & 3;        // col-pair id

    if (MODE == 1) {
        const int tslv = *tsl_ptr;
        #pragma unroll
        for (int mt = 0; mt < 4; ++mt)
            #pragma unroll
            for (int nt = 0; nt < 4; ++nt)
                #pragma unroll
                for (int half = 0; half < 2; ++half) {
                    int row  = m0 + wm * 64 + mt * 16 + qid + half * 8;
                    int gcol = n0 + wn * 32 + nt * 8 + rid * 2;   // even
                    float x1 = acc[mt][nt][2 * half]     + bias[gcol];
                    float x2 = acc[mt][nt][2 * half + 1] + bias[gcol + 1];
                    int hh = gcol >> 7, dd = gcol & 127;
                    float inv = expf((float)dd * (-9.210340371976184f / 128.f));
                    float pos = (float)(tslv - S_LEN + row);
                    float sn, cs;
                    sincosf(pos * inv, &sn, &cs);
                    float y1 = x1 * cs - x2 * sn;
                    float y2 = x1 * sn + x2 * cs;
                    size_t dst = ((size_t)hh * S_LEN + row) * HD + dd;
                    bf16 h1 = __float2bfloat16(y1), h2 = __float2bfloat16(y2);
                    *reinterpret_cast<bf162*>(Ohi + dst) = __halves2bfloat162(h1, h2);
                    bf16 l1 = __float2bfloat16(y1 - __bfloat162float(h1));
                    bf16 l2 = __float2bfloat16(y2 - __bfloat162float(h2));
                    *reinterpret_cast<bf162*>(Olo + dst) = __halves2bfloat162(l1, l2);
                }
    } else if (MODE == 2) {
        #pragma unroll
        for (int mt = 0; mt < 4; ++mt)
            #pragma unroll
            for (int nt = 0; nt < 4; ++nt)
                #pragma unroll
                for (int r = 0; r < 4; ++r) {
                    int row  = m0 + wm * 64 + mt * 16 + qid + (r >> 1) * 8;
                    int gcol = n0 + wn * 32 + nt * 8 + rid * 2 + (r & 1);
                    int hh = gcol >> 7, dd = gcol & 127;
                    float v = acc[mt][nt][r] + bias[gcol];
                    store_split(Ohi, Olo, ((size_t)hh * HD + dd) * S_LEN + row, v);
                }
    } else if (MODE == 3) {
        const float sc = 0.08838834764831845f;
        #pragma unroll
        for (int mt = 0; mt < 4; ++mt)
            #pragma unroll
            for (int nt = 0; nt < 4; ++nt)
                #pragma unroll
                for (int r = 0; r < 4; ++r) {
                    int row  = m0 + wm * 64 + mt * 16 + qid + (r >> 1) * 8;
                    int gcol = n0 + wn * 32 + nt * 8 + rid * 2 + (r & 1);
                    outF[((size_t)hz * S_LEN + row) * S_LEN + gcol] =
                        acc[mt][nt][r] * sc + mask[(size_t)row * S_LEN + gcol];
                }
    } else if (MODE == 4) {
        #pragma unroll
        for (int mt = 0; mt < 4; ++mt)
            #pragma unroll
            for (int nt = 0; nt < 4; ++nt)
                #pragma unroll
                for (int r = 0; r < 4; ++r) {
                    int row  = m0 + wm * 64 + mt * 16 + qid + (r >> 1) * 8;
                    int col  = n0 + wn * 32 + nt * 8 + rid * 2 + (r & 1);
                    store_split(Ohi, Olo,
                                (size_t)row * HID + (size_t)hz * HD + col,
                                acc[mt][nt][r]);
                }
    } else { // MODE 0
        #pragma unroll
        for (int mt = 0; mt < 4; ++mt)
            #pragma unroll
            for (int nt = 0; nt < 4; ++nt)
                #pragma unroll
                for (int r = 0; r < 4; ++r) {
                    int row  = m0 + wm * 64 + mt * 16 + qid + (r >> 1) * 8;
                    int gcol = n0 + wn * 32 + nt * 8 + rid * 2 + (r & 1);
                    outF[(size_t)row * HID + gcol] = acc[mt][nt][r] + bias[gcol];
                }
    }
}

// ===================== fp32 -> bf16 hi/lo split =====================
__global__ void split4_kernel(const float4* __restrict__ src, bf162* __restrict__ hi,
                              bf162* __restrict__ lo, size_t n4)
{
    for (size_t i = blockIdx.x * (size_t)blockDim.x + threadIdx.x; i < n4;
         i += (size_t)gridDim.x * blockDim.x) {
        float4 v = src[i];
        bf16 hx = __float2bfloat16(v.x), hy = __float2bfloat16(v.y);
        bf16 hz2 = __float2bfloat16(v.z), hw = __float2bfloat16(v.w);
        hi[2 * i]     = __halves2bfloat162(hx, hy);
        hi[2 * i + 1] = __halves2bfloat162(hz2, hw);
        lo[2 * i]     = __halves2bfloat162(__float2bfloat16(v.x - __bfloat162float(hx)),
                                           __float2bfloat16(v.y - __bfloat162float(hy)));
        lo[2 * i + 1] = __halves2bfloat162(__float2bfloat16(v.z - __bfloat162float(hz2)),
                                           __float2bfloat16(v.w - __bfloat162float(hw)));
    }
}

// ===================== softmax (rows of g_P) -> split bf16 P =====================
__global__ void __launch_bounds__(256)
softmax_kernel()
{
    const size_t row = blockIdx.x;
    const float* p = g_P + row * S_LEN;
    const int tid = threadIdx.x;

    float v[8];
    float mx = -3.4e38f;
    #pragma unroll
    for (int t = 0; t < 8; ++t) {
        v[t] = p[tid + t * 256];
        mx = fmaxf(mx, v[t]);
    }

    __shared__ float red[8];
    #pragma unroll
    for (int o = 16; o > 0; o >>= 1)
        mx = fmaxf(mx, __shfl_xor_sync(0xffffffffu, mx, o));
    if ((tid & 31) == 0) red[tid >> 5] = mx;
    __syncthreads();
    if (tid == 0) {
        float m = red[0];
        #pragma unroll
        for (int w = 1; w < 8; ++w) m = fmaxf(m, red[w]);
        red[0] = m;
    }
    __syncthreads();
    const float bmax = red[0];
    __syncthreads();

    float sum = 0.f;
    #pragma unroll
    for (int t = 0; t < 8; ++t) { v[t] = expf(v[t] - bmax); sum += v[t]; }
    #pragma unroll
    for (int o = 16; o > 0; o >>= 1)
        sum += __shfl_xor_sync(0xffffffffu, sum, o);
    if ((tid & 31) == 0) red[tid >> 5] = sum;
    __syncthreads();
    if (tid == 0) {
        float s = 0.f;
        #pragma unroll
        for (int w = 0; w < 8; ++w) s += red[w];
        red[0] = 1.f / s;
    }
    __syncthreads();
    const float inv = red[0];
    const size_t base = row * (size_t)S_LEN;
    #pragma unroll
    for (int t = 0; t < 8; ++t)
        store_split(g_Phi, g_Plo, base + tid + t * 256, v[t] * inv);
}

// ===================== launcher =====================
extern "C" void kernel_launch(void* const* d_in, const int* in_sizes, int n_in,
                              void* d_out, int out_size)
{
    const float* X    = (const float*)d_in[0];
    const float* mask = (const float*)d_in[1];
    const float* Wq   = (const float*)d_in[2];
    const float* bq   = (const float*)d_in[3];
    const float* Wk   = (const float*)d_in[4];
    const float* bk   = (const float*)d_in[5];
    const float* Wv   = (const float*)d_in[6];
    const float* bv   = (const float*)d_in[7];
    const float* Wo   = (const float*)d_in[8];
    const float* bo   = (const float*)d_in[9];
    const int*   tsl  = (const int*)d_in[10];
    float* out = (float*)d_out;

    bf16 *pXhi, *pXlo, *pWhi, *pWlo, *pQhi, *pQlo, *pKhi, *pKlo;
    bf16 *pVthi, *pVtlo, *pPhi, *pPlo, *pChi, *pClo;
    float *pP;
    cudaGetSymbolAddress((void**)&pXhi,  g_Xhi);
    cudaGetSymbolAddress((void**)&pXlo,  g_Xlo);
    cudaGetSymbolAddress((void**)&pWhi,  g_Whi);
    cudaGetSymbolAddress((void**)&pWlo,  g_Wlo);
    cudaGetSymbolAddress((void**)&pQhi,  g_Qhi);
    cudaGetSymbolAddress((void**)&pQlo,  g_Qlo);
    cudaGetSymbolAddress((void**)&pKhi,  g_Khi);
    cudaGetSymbolAddress((void**)&pKlo,  g_Klo);
    cudaGetSymbolAddress((void**)&pVthi, g_Vthi);
    cudaGetSymbolAddress((void**)&pVtlo, g_Vtlo);
    cudaGetSymbolAddress((void**)&pP,    g_P);
    cudaGetSymbolAddress((void**)&pPhi,  g_Phi);
    cudaGetSymbolAddress((void**)&pPlo,  g_Plo);
    cudaGetSymbolAddress((void**)&pChi,  g_Chi);
    cudaGetSymbolAddress((void**)&pClo,  g_Clo);

    cudaFuncSetAttribute(mma_gemm<0>, cudaFuncAttributeMaxDynamicSharedMemorySize, SMEM_TOT);
    cudaFuncSetAttribute(mma_gemm<1>, cudaFuncAttributeMaxDynamicSharedMemorySize, SMEM_TOT);
    cudaFuncSetAttribute(mma_gemm<2>, cudaFuncAttributeMaxDynamicSharedMemorySize, SMEM_TOT);
    cudaFuncSetAttribute(mma_gemm<3>, cudaFuncAttributeMaxDynamicSharedMemorySize, SMEM_TOT);
    cudaFuncSetAttribute(mma_gemm<4>, cudaFuncAttributeMaxDynamicSharedMemorySize, SMEM_TOT);

    const size_t WELEM = (size_t)HID * HID;
    split4_kernel<<<2048, 256>>>((const float4*)X,  (bf162*)pXhi, (bf162*)pXlo,
                                 (size_t)S_LEN * HID / 4);
    split4_kernel<<<4096, 256>>>((const float4*)Wq, (bf162*)(pWhi + 0 * WELEM),
                                 (bf162*)(pWlo + 0 * WELEM), WELEM / 4);
    split4_kernel<<<4096, 256>>>((const float4*)Wk, (bf162*)(pWhi + 1 * WELEM),
                                 (bf162*)(pWlo + 1 * WELEM), WELEM / 4);
    split4_kernel<<<4096, 256>>>((const float4*)Wv, (bf162*)(pWhi + 2 * WELEM),
                                 (bf162*)(pWlo + 2 * WELEM), WELEM / 4);
    split4_kernel<<<4096, 256>>>((const float4*)Wo, (bf162*)(pWhi + 3 * WELEM),
                                 (bf162*)(pWlo + 3 * WELEM), WELEM / 4);

    dim3 blk(256);
    dim3 gproj(HID / 128, S_LEN / 128, 1);            // 32 x 16
    mma_gemm<1><<<gproj, blk, SMEM_TOT>>>(pXhi, pXlo, pWhi + 0 * WELEM, pWlo + 0 * WELEM,
                                          HID, 0, 0, bq, nullptr, tsl, nullptr, pQhi, pQlo);
    mma_gemm<1><<<gproj, blk, SMEM_TOT>>>(pXhi, pXlo, pWhi + 1 * WELEM, pWlo + 1 * WELEM,
                                          HID, 0, 0, bk, nullptr, tsl, nullptr, pKhi, pKlo);
    mma_gemm<2><<<gproj, blk, SMEM_TOT>>>(pXhi, pXlo, pWhi + 2 * WELEM, pWlo + 2 * WELEM,
                                          HID, 0, 0, bv, nullptr, nullptr, nullptr, pVthi, pVtlo);

    dim3 gsc(S_LEN / 128, S_LEN / 128, NH);           // 16 x 16 x 32
    mma_gemm<3><<<gsc, blk, SMEM_TOT>>>(pQhi, pQlo, pKhi, pKlo,
                                        HD, (long long)S_LEN * HD, (long long)S_LEN * HD,
                                        nullptr, mask, nullptr, pP, nullptr, nullptr);

    softmax_kernel<<<NH * S_LEN, 256>>>();

    dim3 gpv(1, S_LEN / 128, NH);                     // 1 x 16 x 32
    mma_gemm<4><<<gpv, blk, SMEM_TOT>>>(pPhi, pPlo, pVthi, pVtlo,
                                        S_LEN, (long long)S_LEN * S_LEN, (long long)HD * S_LEN,
                                        nullptr, nullptr, nullptr, nullptr, pChi, pClo);

    mma_gemm<0><<<gproj, blk, SMEM_TOT>>>(pChi, pClo, pWhi + 3 * WELEM, pWlo + 3 * WELEM,
                                          HID, 0, 0, bo, nullptr, nullptr, out, nullptr, nullptr);
}

// round 16
// speedup vs baseline: 1.0016x; 1.0013x over previous
#include <cuda_runtime.h>
#include <cuda_bf16.h>
#include <math.h>
#include <stdint.h>

#define S_LEN 2048
#define HID   4096
#define NH    32
#define HD    128

typedef __nv_bfloat16  bf16;
typedef __nv_bfloat162 bf162;

// ===================== scratch (device globals; no cudaMalloc) =====================
__device__ bf16 g_Xhi[(size_t)S_LEN * HID];
__device__ bf16 g_Xlo[(size_t)S_LEN * HID];
__device__ bf16 g_Whi[4][(size_t)HID * HID];
__device__ bf16 g_Wlo[4][(size_t)HID * HID];
__device__ bf16 g_Qhi[(size_t)NH * S_LEN * HD];
__device__ bf16 g_Qlo[(size_t)NH * S_LEN * HD];
__device__ bf16 g_Khi[(size_t)NH * S_LEN * HD];
__device__ bf16 g_Klo[(size_t)NH * S_LEN * HD];
__device__ bf16 g_Vthi[(size_t)NH * HD * S_LEN];   // [h][d][t]
__device__ bf16 g_Vtlo[(size_t)NH * HD * S_LEN];
__device__ float g_P  [(size_t)NH * S_LEN * S_LEN];
__device__ bf16 g_Phi [(size_t)NH * S_LEN * S_LEN];
__device__ bf16 g_Plo [(size_t)NH * S_LEN * S_LEN];
__device__ bf16 g_Chi [(size_t)S_LEN * HID];
__device__ bf16 g_Clo [(size_t)S_LEN * HID];

// ===================== helpers =====================
static __device__ __forceinline__ uint32_t smem_u32(const void* p) {
    uint32_t a;
    asm("{ .reg .u64 t; cvta.to.shared.u64 t, %1; cvt.u32.u64 %0, t; }" : "=r"(a) : "l"(p));
    return a;
}

static __device__ __forceinline__ void cp_async16(uint32_t dst, const void* src) {
    asm volatile("cp.async.cg.shared.global [%0], [%1], 16;" :: "r"(dst), "l"(src));
}
#define CP_COMMIT()  asm volatile("cp.async.commit_group;" ::: "memory")
#define CP_WAIT(n)   asm volatile("cp.async.wait_group %0;" :: "n"(n) : "memory")

static __device__ __forceinline__ void ldsm_x4(uint32_t addr, uint32_t& r0, uint32_t& r1,
                                               uint32_t& r2, uint32_t& r3) {
    asm volatile("ldmatrix.sync.aligned.m8n8.x4.shared.b16 {%0,%1,%2,%3}, [%4];"
                 : "=r"(r0), "=r"(r1), "=r"(r2), "=r"(r3) : "r"(addr));
}

static __device__ __forceinline__ void mma16816(float* c, const uint32_t* a, const uint32_t* b) {
    asm volatile(
        "mma.sync.aligned.m16n8k16.row.col.f32.bf16.bf16.f32 "
        "{%0,%1,%2,%3}, {%4,%5,%6,%7}, {%8,%9}, {%0,%1,%2,%3};"
        : "+f"(c[0]), "+f"(c[1]), "+f"(c[2]), "+f"(c[3])
        : "r"(a[0]), "r"(a[1]), "r"(a[2]), "r"(a[3]), "r"(b[0]), "r"(b[1]));
}

static __device__ __forceinline__ void store_split(bf16* hi, bf16* lo, size_t idx, float v) {
    bf16 h = __float2bfloat16(v);
    hi[idx] = h;
    lo[idx] = __float2bfloat16(v - __bfloat162float(h));
}

// smem tile geometry: 128 rows x 32 bf16, row pitch 40 bf16 (80 B = 5 x 16B, odd -> ldmatrix conflict-free)
#define PITCH    40
#define TILE_B   (128 * PITCH * 2)      // 10240 bytes
#define STAGE_B  (4 * TILE_B)           // Ahi, Alo, Bhi, Blo = 40960 bytes
#define SMEM_TOT (2 * STAGE_B)          // double buffered = 81920 bytes

// ===================== split-bf16 mma.sync GEMM-NT =====================
// D[m][n] = sum_k A[m][k] * B[n][k]   (A,B hi/lo bf16 pairs, K-major, ld = K)
// MODE 0: fp32 out [M,HID] + bias                 (O projection)
// MODE 1: +bias, RoPE, split-store [h][s][d]      (Q / K)
// MODE 2: +bias, split-store transposed [h][d][t] (V)
// MODE 3: *1/sqrt(128) + mask -> fp32 g_P         (scores)
// MODE 4: split-store ctx [s][HID]                (PV)
template<int MODE>
__global__ void __launch_bounds__(256, 1)
mma_gemm(const bf16* __restrict__ Ahi, const bf16* __restrict__ Alo,
         const bf16* __restrict__ Bhi, const bf16* __restrict__ Blo,
         int K, long long batchA, long long batchB,
         const float* __restrict__ bias, const float* __restrict__ mask,
         const int* __restrict__ tsl_ptr,
         float* __restrict__ outF, bf16* __restrict__ Ohi, bf16* __restrict__ Olo)
{
    extern __shared__ char smem[];
    const uint32_t sbase = smem_u32(smem);

    const int tid  = threadIdx.x;
    const int wid  = tid >> 5;
    const int lane = tid & 31;
    const int wm   = wid >> 2;          // 0..1  -> 64-row slab
    const int wn   = wid & 3;           // 0..3  -> 32-col slab
    const int hz   = blockIdx.z;
    const int m0   = blockIdx.y * 128;
    const int n0   = blockIdx.x * 128;

    const bf16* srcs[4] = {
        Ahi + (size_t)hz * batchA + (size_t)m0 * K,
        Alo + (size_t)hz * batchA + (size_t)m0 * K,
        Bhi + (size_t)hz * batchB + (size_t)n0 * K,
        Blo + (size_t)hz * batchB + (size_t)n0 * K
    };

    // per-thread load slots: idx 0..511 -> row idx>>2, 16B-chunk idx&3
    const int l_r0 = tid >> 2,       l_c = (tid & 3) * 8;     // bf16 col offset
    const int l_r1 = (tid + 256) >> 2;

    auto load_stage = [&](int kc, int b) {
        const uint32_t stage = sbase + b * STAGE_B;
        #pragma unroll
        for (int t = 0; t < 4; ++t) {
            const bf16* s = srcs[t] + (size_t)kc * 32;
            const uint32_t dtile = stage + t * TILE_B;
            cp_async16(dtile + (l_r0 * PITCH + l_c) * 2, s + (size_t)l_r0 * K + l_c);
            cp_async16(dtile + (l_r1 * PITCH + l_c) * 2, s + (size_t)l_r1 * K + l_c);
        }
    };

    float acc[4][4][4];
    #pragma unroll
    for (int i = 0; i < 4; ++i)
        #pragma unroll
        for (int j = 0; j < 4; ++j)
            #pragma unroll
            for (int r = 0; r < 4; ++r) acc[i][j][r] = 0.f;

    const int NC = K >> 5;
    load_stage(0, 0);
    CP_COMMIT();

    // ldmatrix per-lane address offsets
    const int a_row  = lane & 15;                    // + mt*16 + wm*64
    const int a_koff = (lane & 16) ? 8 : 0;
    const int b_row  = (lane & 7) + ((lane & 16) ? 8 : 0);   // + pair*16 + wn*32
    const int b_koff = (lane & 8) ? 8 : 0;

    for (int kc = 0; kc < NC; ++kc) {
        if (kc + 1 < NC) { load_stage(kc + 1, (kc + 1) & 1); CP_COMMIT(); CP_WAIT(1); }
        else             { CP_WAIT(0); }
        __syncthreads();

        const uint32_t stage = sbase + (kc & 1) * STAGE_B;
        const uint32_t sAh = stage;
        const uint32_t sAl = stage + TILE_B;
        const uint32_t sBh = stage + 2 * TILE_B;
        const uint32_t sBl = stage + 3 * TILE_B;

        #pragma unroll
        for (int ks = 0; ks < 32; ks += 16) {
            uint32_t a_hi[4][4], a_lo[4][4], b_hi[4][2], b_lo[4][2];
            #pragma unroll
            for (int mt = 0; mt < 4; ++mt) {
                const uint32_t off =
                    ((wm * 64 + mt * 16 + a_row) * PITCH + ks + a_koff) * 2;
                ldsm_x4(sAh + off, a_hi[mt][0], a_hi[mt][1], a_hi[mt][2], a_hi[mt][3]);
                ldsm_x4(sAl + off, a_lo[mt][0], a_lo[mt][1], a_lo[mt][2], a_lo[mt][3]);
            }
            #pragma unroll
            for (int pr = 0; pr < 2; ++pr) {
                const uint32_t off =
                    ((wn * 32 + pr * 16 + b_row) * PITCH + ks + b_koff) * 2;
                ldsm_x4(sBh + off, b_hi[2 * pr][0], b_hi[2 * pr][1],
                                   b_hi[2 * pr + 1][0], b_hi[2 * pr + 1][1]);
                ldsm_x4(sBl + off, b_lo[2 * pr][0], b_lo[2 * pr][1],
                                   b_lo[2 * pr + 1][0], b_lo[2 * pr + 1][1]);
            }
            #pragma unroll
            for (int mt = 0; mt < 4; ++mt)
                #pragma unroll
                for (int nt = 0; nt < 4; ++nt) {
                    mma16816(acc[mt][nt], a_hi[mt], b_hi[nt]);
                    mma16816(acc[mt][nt], a_hi[mt], b_lo[nt]);
                    mma16816(acc[mt][nt], a_lo[mt], b_hi[nt]);
                }
        }
        __syncthreads();
    }

    // ===================== epilogue (straight from registers) =====================
    const int qid = lane >> 2;       // row within 8
    const int rid = lane & 3;        // col-pair id

    if (MODE == 1) {
        const int tslv = *tsl_ptr;
        #pragma unroll
        for (int mt = 0; mt < 4; ++mt)
            #pragma unroll
            for (int nt = 0; nt < 4; ++nt)
                #pragma unroll
                for (int half = 0; half < 2; ++half) {
                    int row  = m0 + wm * 64 + mt * 16 + qid + half * 8;
                    int gcol = n0 + wn * 32 + nt * 8 + rid * 2;   // even
                    float x1 = acc[mt][nt][2 * half]     + bias[gcol];
                    float x2 = acc[mt][nt][2 * half + 1] + bias[gcol + 1];
                    int hh = gcol >> 7, dd = gcol & 127;
                    float inv = expf((float)dd * (-9.210340371976184f / 128.f));
                    float pos = (float)(tslv - S_LEN + row);
                    float sn, cs;
                    sincosf(pos * inv, &sn, &cs);
                    float y1 = x1 * cs - x2 * sn;
                    float y2 = x1 * sn + x2 * cs;
                    size_t dst = ((size_t)hh * S_LEN + row) * HD + dd;
                    bf16 h1 = __float2bfloat16(y1), h2 = __float2bfloat16(y2);
                    *reinterpret_cast<bf162*>(Ohi + dst) = __halves2bfloat162(h1, h2);
                    bf16 l1 = __float2bfloat16(y1 - __bfloat162float(h1));
                    bf16 l2 = __float2bfloat16(y2 - __bfloat162float(h2));
                    *reinterpret_cast<bf162*>(Olo + dst) = __halves2bfloat162(l1, l2);
                }
    } else if (MODE == 2) {
        #pragma unroll
        for (int mt = 0; mt < 4; ++mt)
            #pragma unroll
            for (int nt = 0; nt < 4; ++nt)
                #pragma unroll
                for (int r = 0; r < 4; ++r) {
                    int row  = m0 + wm * 64 + mt * 16 + qid + (r >> 1) * 8;
                    int gcol = n0 + wn * 32 + nt * 8 + rid * 2 + (r & 1);
                    int hh = gcol >> 7, dd = gcol & 127;
                    float v = acc[mt][nt][r] + bias[gcol];
                    store_split(Ohi, Olo, ((size_t)hh * HD + dd) * S_LEN + row, v);
                }
    } else if (MODE == 3) {
        const float sc = 0.08838834764831845f;
        #pragma unroll
        for (int mt = 0; mt < 4; ++mt)
            #pragma unroll
            for (int nt = 0; nt < 4; ++nt)
                #pragma unroll
                for (int r = 0; r < 4; ++r) {
                    int row  = m0 + wm * 64 + mt * 16 + qid + (r >> 1) * 8;
                    int gcol = n0 + wn * 32 + nt * 8 + rid * 2 + (r & 1);
                    outF[((size_t)hz * S_LEN + row) * S_LEN + gcol] =
                        acc[mt][nt][r] * sc + mask[(size_t)row * S_LEN + gcol];
                }
    } else if (MODE == 4) {
        #pragma unroll
        for (int mt = 0; mt < 4; ++mt)
            #pragma unroll
            for (int nt = 0; nt < 4; ++nt)
                #pragma unroll
                for (int r = 0; r < 4; ++r) {
                    int row  = m0 + wm * 64 + mt * 16 + qid + (r >> 1) * 8;
                    int col  = n0 + wn * 32 + nt * 8 + rid * 2 + (r & 1);
                    store_split(Ohi, Olo,
                                (size_t)row * HID + (size_t)hz * HD + col,
                                acc[mt][nt][r]);
                }
    } else { // MODE 0
        #pragma unroll
        for (int mt = 0; mt < 4; ++mt)
            #pragma unroll
            for (int nt = 0; nt < 4; ++nt)
                #pragma unroll
                for (int r = 0; r < 4; ++r) {
                    int row  = m0 + wm * 64 + mt * 16 + qid + (r >> 1) * 8;
                    int gcol = n0 + wn * 32 + nt * 8 + rid * 2 + (r & 1);
                    outF[(size_t)row * HID + gcol] = acc[mt][nt][r] + bias[gcol];
                }
    }
}

// ===================== fp32 -> bf16 hi/lo split =====================
__global__ void split4_kernel(const float4* __restrict__ src, bf162* __restrict__ hi,
                              bf162* __restrict__ lo, size_t n4)
{
    for (size_t i = blockIdx.x * (size_t)blockDim.x + threadIdx.x; i < n4;
         i += (size_t)gridDim.x * blockDim.x) {
        float4 v = src[i];
        bf16 hx = __float2bfloat16(v.x), hy = __float2bfloat16(v.y);
        bf16 hz2 = __float2bfloat16(v.z), hw = __float2bfloat16(v.w);
        hi[2 * i]     = __halves2bfloat162(hx, hy);
        hi[2 * i + 1] = __halves2bfloat162(hz2, hw);
        lo[2 * i]     = __halves2bfloat162(__float2bfloat16(v.x - __bfloat162float(hx)),
                                           __float2bfloat16(v.y - __bfloat162float(hy)));
        lo[2 * i + 1] = __halves2bfloat162(__float2bfloat16(v.z - __bfloat162float(hz2)),
                                           __float2bfloat16(v.w - __bfloat162float(hw)));
    }
}

// ===================== softmax (rows of g_P) -> split bf16 P =====================
__global__ void __launch_bounds__(256)
softmax_kernel()
{
    const size_t row = blockIdx.x;
    const float* p = g_P + row * S_LEN;
    const int tid = threadIdx.x;

    float v[8];
    float mx = -3.4e38f;
    #pragma unroll
    for (int t = 0; t < 8; ++t) {
        v[t] = p[tid + t * 256];
        mx = fmaxf(mx, v[t]);
    }

    __shared__ float red[8];
    #pragma unroll
    for (int o = 16; o > 0; o >>= 1)
        mx = fmaxf(mx, __shfl_xor_sync(0xffffffffu, mx, o));
    if ((tid & 31) == 0) red[tid >> 5] = mx;
    __syncthreads();
    if (tid == 0) {
        float m = red[0];
        #pragma unroll
        for (int w = 1; w < 8; ++w) m = fmaxf(m, red[w]);
        red[0] = m;
    }
    __syncthreads();
    const float bmax = red[0];
    __syncthreads();

    float sum = 0.f;
    #pragma unroll
    for (int t = 0; t < 8; ++t) { v[t] = expf(v[t] - bmax); sum += v[t]; }
    #pragma unroll
    for (int o = 16; o > 0; o >>= 1)
        sum += __shfl_xor_sync(0xffffffffu, sum, o);
    if ((tid & 31) == 0) red[tid >> 5] = sum;
    __syncthreads();
    if (tid == 0) {
        float s = 0.f;
        #pragma unroll
        for (int w = 0; w < 8; ++w) s += red[w];
        red[0] = 1.f / s;
    }
    __syncthreads();
    const float inv = red[0];
    const size_t base = row * (size_t)S_LEN;
    #pragma unroll
    for (int t = 0; t < 8; ++t)
        store_split(g_Phi, g_Plo, base + tid + t * 256, v[t] * inv);
}

// ===================== launcher =====================
extern "C" void kernel_launch(void* const* d_in, const int* in_sizes, int n_in,
                              void* d_out, int out_size)
{
    const float* X    = (const float*)d_in[0];
    const float* mask = (const float*)d_in[1];
    const float* Wq   = (const float*)d_in[2];
    const float* bq   = (const float*)d_in[3];
    const float* Wk   = (const float*)d_in[4];
    const float* bk   = (const float*)d_in[5];
    const float* Wv   = (const float*)d_in[6];
    const float* bv   = (const float*)d_in[7];
    const float* Wo   = (const float*)d_in[8];
    const float* bo   = (const float*)d_in[9];
    const int*   tsl  = (const int*)d_in[10];
    float* out = (float*)d_out;

    bf16 *pXhi, *pXlo, *pWhi, *pWlo, *pQhi, *pQlo, *pKhi, *pKlo;
    bf16 *pVthi, *pVtlo, *pPhi, *pPlo, *pChi, *pClo;
    float *pP;
    cudaGetSymbolAddress((void**)&pXhi,  g_Xhi);
    cudaGetSymbolAddress((void**)&pXlo,  g_Xlo);
    cudaGetSymbolAddress((void**)&pWhi,  g_Whi);
    cudaGetSymbolAddress((void**)&pWlo,  g_Wlo);
    cudaGetSymbolAddress((void**)&pQhi,  g_Qhi);
    cudaGetSymbolAddress((void**)&pQlo,  g_Qlo);
    cudaGetSymbolAddress((void**)&pKhi,  g_Khi);
    cudaGetSymbolAddress((void**)&pKlo,  g_Klo);
    cudaGetSymbolAddress((void**)&pVthi, g_Vthi);
    cudaGetSymbolAddress((void**)&pVtlo, g_Vtlo);
    cudaGetSymbolAddress((void**)&pP,    g_P);
    cudaGetSymbolAddress((void**)&pPhi,  g_Phi);
    cudaGetSymbolAddress((void**)&pPlo,  g_Plo);
    cudaGetSymbolAddress((void**)&pChi,  g_Chi);
    cudaGetSymbolAddress((void**)&pClo,  g_Clo);

    cudaFuncSetAttribute(mma_gemm<0>, cudaFuncAttributeMaxDynamicSharedMemorySize, SMEM_TOT);
    cudaFuncSetAttribute(mma_gemm<1>, cudaFuncAttributeMaxDynamicSharedMemorySize, SMEM_TOT);
    cudaFuncSetAttribute(mma_gemm<2>, cudaFuncAttributeMaxDynamicSharedMemorySize, SMEM_TOT);
    cudaFuncSetAttribute(mma_gemm<3>, cudaFuncAttributeMaxDynamicSharedMemorySize, SMEM_TOT);
    cudaFuncSetAttribute(mma_gemm<4>, cudaFuncAttributeMaxDynamicSharedMemorySize, SMEM_TOT);

    const size_t WELEM = (size_t)HID * HID;
    split4_kernel<<<2048, 256>>>((const float4*)X,  (bf162*)pXhi, (bf162*)pXlo,
                                 (size_t)S_LEN * HID / 4);
    split4_kernel<<<4096, 256>>>((const float4*)Wq, (bf162*)(pWhi + 0 * WELEM),
                                 (bf162*)(pWlo + 0 * WELEM), WELEM / 4);
    split4_kernel<<<4096, 256>>>((const float4*)Wk, (bf162*)(pWhi + 1 * WELEM),
                                 (bf162*)(pWlo + 1 * WELEM), WELEM / 4);
    split4_kernel<<<4096, 256>>>((const float4*)Wv, (bf162*)(pWhi + 2 * WELEM),
                                 (bf162*)(pWlo + 2 * WELEM), WELEM / 4);
    split4_kernel<<<4096, 256>>>((const float4*)Wo, (bf162*)(pWhi + 3 * WELEM),
                                 (bf162*)(pWlo + 3 * WELEM), WELEM / 4);

    dim3 blk(256);
    dim3 gproj(HID / 128, S_LEN / 128, 1);            // 32 x 16
    mma_gemm<1><<<gproj, blk, SMEM_TOT>>>(pXhi, pXlo, pWhi + 0 * WELEM, pWlo + 0 * WELEM,
                                          HID, 0, 0, bq, nullptr, tsl, nullptr, pQhi, pQlo);
    mma_gemm<1><<<gproj, blk, SMEM_TOT>>>(pXhi, pXlo, pWhi + 1 * WELEM, pWlo + 1 * WELEM,
                                          HID, 0, 0, bk, nullptr, tsl, nullptr, pKhi, pKlo);
    mma_gemm<2><<<gproj, blk, SMEM_TOT>>>(pXhi, pXlo, pWhi + 2 * WELEM, pWlo + 2 * WELEM,
                                          HID, 0, 0, bv, nullptr, nullptr, nullptr, pVthi, pVtlo);

    dim3 gsc(S_LEN / 128, S_LEN / 128, NH);           // 16 x 16 x 32
    mma_gemm<3><<<gsc, blk, SMEM_TOT>>>(pQhi, pQlo, pKhi, pKlo,
                                        HD, (long long)S_LEN * HD, (long long)S_LEN * HD,
                                        nullptr, mask, nullptr, pP, nullptr, nullptr);

    softmax_kernel<<<NH * S_LEN, 256>>>();

    dim3 gpv(1, S_LEN / 128, NH);                     // 1 x 16 x 32
    mma_gemm<4><<<gpv, blk, SMEM_TOT>>>(pPhi, pPlo, pVthi, pVtlo,
                                        S_LEN, (long long)S_LEN * S_LEN, (long long)HD * S_LEN,
                                        nullptr, nullptr, nullptr, nullptr, pChi, pClo);

    mma_gemm<0><<<gproj, blk, SMEM_TOT>>>(pChi, pClo, pWhi + 3 * WELEM, pWlo + 3 * WELEM,
                                          HID, 0, 0, bo, nullptr, nullptr, out, nullptr, nullptr);
}